// round 9
// baseline (speedup 1.0000x reference)
#include <cuda_runtime.h>
#include <math.h>
#include <stdint.h>

#define DMODEL 512
#define NHEAD 8
#define HD 64
#define MAXS 4096

// Scratch (no allocations allowed) — __device__ globals.
__device__ float g_Q[MAXS * DMODEL];
__device__ float g_K[MAXS * DMODEL];
__device__ float g_V[MAXS * DMODEL];
__device__ float g_AO[MAXS * DMODEL];
__device__ float g_T1[MAXS * DMODEL];

__device__ __forceinline__ uint32_t f2tf(float f) {
    uint32_t u;
    asm("cvt.rna.tf32.f32 %0, %1;" : "=r"(u) : "f"(f));
    return u;
}

__device__ __forceinline__ void mma_tf32(float* c, const uint32_t* a,
                                         uint32_t b0, uint32_t b1) {
    asm volatile(
        "mma.sync.aligned.m16n8k8.row.col.f32.tf32.tf32.f32 "
        "{%0,%1,%2,%3}, {%4,%5,%6,%7}, {%8,%9}, {%0,%1,%2,%3};\n"
        : "+f"(c[0]), "+f"(c[1]), "+f"(c[2]), "+f"(c[3])
        : "r"(a[0]), "r"(a[1]), "r"(a[2]), "r"(a[3]), "r"(b0), "r"(b1));
}

__device__ __forceinline__ void ldsm_x4(uint32_t& r0, uint32_t& r1,
                                        uint32_t& r2, uint32_t& r3,
                                        uint32_t addr) {
    asm volatile("ldmatrix.sync.aligned.m8n8.x4.shared.b16 {%0,%1,%2,%3}, [%4];"
                 : "=r"(r0), "=r"(r1), "=r"(r2), "=r"(r3) : "r"(addr));
}

__device__ __forceinline__ uint32_t s2u(const void* p) {
    return (uint32_t)__cvta_generic_to_shared(p);
}

__device__ __forceinline__ void cp_async16(uint32_t smem_addr, const void* gptr) {
    asm volatile("cp.async.ca.shared.global [%0], [%1], 16;"
                 :: "r"(smem_addr), "l"(gptr));
}
__device__ __forceinline__ void cp_commit() {
    asm volatile("cp.async.commit_group;");
}
template <int N>
__device__ __forceinline__ void cp_wait() {
    asm volatile("cp.async.wait_group %0;" :: "n"(N));
}

// ============================================================================
// GEMM body: block tile 128x64, BK=32, 256 threads = 8 warps (4m x 2n).
// Warp tile 32x32 (2 m16 x 4 n8). A staged in smem (tf32, XOR swizzle over
// 8 chunks/row), reg-prefetched one iteration ahead; B frags straight from
// L2 with one-ks-ahead prefetch.
// MODE 0: fp32 out + bias; 1: tf32-rounded bits; 2: *0.125 then tf32 bits.
// ============================================================================
template <int MODE>
__device__ __forceinline__ void gemm_body(
    const float* __restrict__ A, const float* __restrict__ B,
    float* __restrict__ C, const float* __restrict__ bias,
    int M, int N, int K, int bm, int bn, uint32_t* As /* 128*32 words */)
{
    const int tid = threadIdx.x;
    const int w = tid >> 5, lane = tid & 31;
    const int g = lane >> 2, q = lane & 3;
    const int wm = w >> 1, wn = w & 1;
    const int n0 = bn + (wn << 5);

    float acc[2][4][4];
#pragma unroll
    for (int mb = 0; mb < 2; mb++)
#pragma unroll
        for (int t = 0; t < 4; t++)
#pragma unroll
            for (int i = 0; i < 4; i++) acc[mb][t][i] = 0.f;

    const uint32_t asb = s2u(As);
    const int tp = lane >> 3;
    const int arow_l = ((tp & 1) << 3) + (lane & 7);

    // A staging: 128 rows x 8 chunks (float4) = 1024 float4, 4 per thread.
    float4 aReg[4];
#pragma unroll
    for (int p = 0; p < 4; p++) {
        int f = tid + (p << 8);
        int r = f >> 3, c = f & 7;
        aReg[p] = *(const float4*)(A + (size_t)(bm + r) * K + (c << 2));
    }

    // B fragment prefetch for (k0=0, ks=0)
    float br[4][2];
    {
        const float* bp0 = B + (size_t)q * N + n0 + g;
#pragma unroll
        for (int t = 0; t < 4; t++) {
            br[t][0] = __ldg(bp0 + (t << 3));
            br[t][1] = __ldg(bp0 + (t << 3) + 4 * N);
        }
    }

    for (int k0 = 0; k0 < K; k0 += 32) {
        __syncthreads();
#pragma unroll
        for (int p = 0; p < 4; p++) {
            int f = tid + (p << 8);
            int r = f >> 3, c = f & 7;
            uint32_t* dst = &As[(r << 5) + ((c ^ (r & 7)) << 2)];
            *(uint4*)dst = make_uint4(f2tf(aReg[p].x), f2tf(aReg[p].y),
                                      f2tf(aReg[p].z), f2tf(aReg[p].w));
        }
        __syncthreads();

        const bool more = (k0 + 32) < K;
        if (more) {
#pragma unroll
            for (int p = 0; p < 4; p++) {
                int f = tid + (p << 8);
                int r = f >> 3, c = f & 7;
                aReg[p] = *(const float4*)(A + (size_t)(bm + r) * K + k0 + 32 + (c << 2));
            }
        }

#pragma unroll
        for (int ks = 0; ks < 4; ks++) {
            uint32_t bf[4][2];
#pragma unroll
            for (int t = 0; t < 4; t++) {
                bf[t][0] = f2tf(br[t][0]);
                bf[t][1] = f2tf(br[t][1]);
            }
            int knext = (ks < 3) ? (k0 + ((ks + 1) << 3)) : (more ? (k0 + 32) : 0);
            {
                const float* bpn = B + (size_t)(knext + q) * N + n0 + g;
#pragma unroll
                for (int t = 0; t < 4; t++) {
                    br[t][0] = __ldg(bpn + (t << 3));
                    br[t][1] = __ldg(bpn + (t << 3) + 4 * N);
                }
            }
            uint32_t a[2][4];
#pragma unroll
            for (int mb = 0; mb < 2; mb++) {
                int r = (wm << 5) + (mb << 4) + arow_l;
                int ch = (ks << 1) + (tp >> 1);
                uint32_t addr = asb + (((r << 5) + ((ch ^ (r & 7)) << 2)) << 2);
                ldsm_x4(a[mb][0], a[mb][1], a[mb][2], a[mb][3], addr);
            }
#pragma unroll
            for (int mb = 0; mb < 2; mb++)
#pragma unroll
                for (int t = 0; t < 4; t++)
                    mma_tf32(acc[mb][t], a[mb], bf[t][0], bf[t][1]);
        }
    }

#pragma unroll
    for (int mb = 0; mb < 2; mb++) {
        int row = bm + (wm << 5) + (mb << 4) + g;
#pragma unroll
        for (int t = 0; t < 4; t++) {
            int col = n0 + (t << 3) + (q << 1);
            float b0 = 0.f, b1 = 0.f;
            if (MODE == 0 && bias) { b0 = bias[col]; b1 = bias[col + 1]; }
            float2 v0 = make_float2(acc[mb][t][0] + b0, acc[mb][t][1] + b1);
            float2 v1 = make_float2(acc[mb][t][2] + b0, acc[mb][t][3] + b1);
            if (MODE == 1) {
                v0.x = __uint_as_float(f2tf(v0.x));
                v0.y = __uint_as_float(f2tf(v0.y));
                v1.x = __uint_as_float(f2tf(v1.x));
                v1.y = __uint_as_float(f2tf(v1.y));
            } else if (MODE == 2) {
                v0.x = __uint_as_float(f2tf(v0.x * 0.125f));
                v0.y = __uint_as_float(f2tf(v0.y * 0.125f));
                v1.x = __uint_as_float(f2tf(v1.x * 0.125f));
                v1.y = __uint_as_float(f2tf(v1.y * 0.125f));
            }
            *(float2*)(C + (size_t)row * N + col) = v0;
            *(float2*)(C + (size_t)(row + 8) * N + col) = v1;
        }
    }
}

// Plain GEMM (Wo projections), fp32 out + bias. Grid (N/64, M/128).
__global__ __launch_bounds__(256, 2) void gemm_tc_kernel(
    const float* __restrict__ A, const float* __restrict__ B,
    float* __restrict__ C, const float* __restrict__ bias,
    int M, int N, int K)
{
    __shared__ uint32_t As[128 * 32];
    gemm_body<0>(A, B, C, bias, M, N, K, blockIdx.y << 7, blockIdx.x << 6, As);
}

// Fused QKV projections: 3 segments x 8 n-blocks x (M/128); one launch.
__global__ __launch_bounds__(256, 2) void qkv_gemm_kernel(
    const float* __restrict__ Xq, const float* __restrict__ Xk,
    const float* __restrict__ Xv,
    const float* __restrict__ Wq, const float* __restrict__ Wk,
    const float* __restrict__ Wv,
    float* __restrict__ Qo, float* __restrict__ Ko, float* __restrict__ Vo,
    int M, int K)
{
    __shared__ uint32_t As[128 * 32];
    const int seg = blockIdx.x >> 3;
    const int bn = (blockIdx.x & 7) << 6;
    const int bm = blockIdx.y << 7;
    if (seg == 0)
        gemm_body<2>(Xq, Wq, Qo, nullptr, M, DMODEL, K, bm, bn, As);
    else if (seg == 1)
        gemm_body<1>(Xk, Wk, Ko, nullptr, M, DMODEL, K, bm, bn, As);
    else
        gemm_body<1>(Xv, Wv, Vo, nullptr, M, DMODEL, K, bm, bn, As);
}

// ============================================================================
// Flash attention (unchanged from round 8): tf32 mma, 32 q-rows/warp,
// cp.async double-buffered K/V, 64-key tiles processed as two 32-key halves.
// Smem (96KB dynamic): Kbuf 2x16KB | Vbuf 2x16KB | Ps 32KB.
// ============================================================================
__global__ __launch_bounds__(128, 2) void attn_tc_kernel(
    const float* __restrict__ Q, const float* __restrict__ K,
    const float* __restrict__ V, float* __restrict__ O, int S)
{
    extern __shared__ uint32_t sh[];
    uint32_t* Ps = sh + 16384;

    const int tid = threadIdx.x;
    const int w = tid >> 5, lane = tid & 31;
    const int g = lane >> 2, q = lane & 3;
    const int head = blockIdx.y;
    const int q0 = blockIdx.x << 7;
    const int rowW = q0 + (w << 5);

    const int tp = lane >> 3;
    const int kb_row = ((tp >> 1) << 3) + (lane & 7);
    const int pa_row = ((tp & 1) << 3) + (lane & 7);

    const uint32_t shb = s2u(sh);
    const uint32_t pwb = shb + (16384 << 2) + (w << 13);
    uint32_t* Pw = Ps + (w << 11);

    const float* Kg0 = K + head * HD;
    const float* Vg0 = V + head * HD;

    uint32_t aq[2][8][4];
#pragma unroll
    for (int mb = 0; mb < 2; mb++) {
        const float* Q0 = Q + (size_t)(rowW + (mb << 4) + g) * DMODEL + head * HD;
        const float* Q1 = Q0 + 8 * DMODEL;
#pragma unroll
        for (int kk = 0; kk < 8; kk++) {
            aq[mb][kk][0] = __float_as_uint(Q0[8 * kk + q]);
            aq[mb][kk][1] = __float_as_uint(Q1[8 * kk + q]);
            aq[mb][kk][2] = __float_as_uint(Q0[8 * kk + q + 4]);
            aq[mb][kk][3] = __float_as_uint(Q1[8 * kk + q + 4]);
        }
    }

    float o[2][8][4];
#pragma unroll
    for (int mb = 0; mb < 2; mb++)
#pragma unroll
        for (int t = 0; t < 8; t++)
#pragma unroll
            for (int i = 0; i < 4; i++) o[mb][t][i] = 0.f;
    float m0[2] = { -1e30f, -1e30f }, m1[2] = { -1e30f, -1e30f };
    float l0[2] = { 0.f, 0.f }, l1[2] = { 0.f, 0.f };

    const int nkb = S >> 6;

    auto stage = [&](int kb, int buf) {
        const float* Kg = Kg0 + (size_t)(kb << 6) * DMODEL;
        const float* Vg = Vg0 + (size_t)(kb << 6) * DMODEL;
        uint32_t kd = shb + (buf << 14);
        uint32_t vd = shb + (8192 << 2) + (buf << 14);
#pragma unroll
        for (int f = tid; f < 1024; f += 128) {
            int r = f >> 4, c4 = f & 15;
            uint32_t off = (((r << 6) + ((c4 ^ (r & 15)) << 2)) << 2);
            cp_async16(kd + off, Kg + (size_t)r * DMODEL + (c4 << 2));
            cp_async16(vd + off, Vg + (size_t)r * DMODEL + (c4 << 2));
        }
    };

    stage(0, 0);
    cp_commit();

    for (int kb = 0; kb < nkb; kb++) {
        const int cur = kb & 1;
        if (kb + 1 < nkb) {
            stage(kb + 1, cur ^ 1);
            cp_commit();
            cp_wait<1>();
        } else {
            cp_wait<0>();
        }
        __syncthreads();

        const uint32_t ksb = shb + (cur << 14);
        const uint32_t* Vs = sh + 8192 + (cur << 12);

#pragma unroll
        for (int h = 0; h < 2; h++) {
            float sc[2][4][4];
#pragma unroll
            for (int mb = 0; mb < 2; mb++)
#pragma unroll
                for (int t = 0; t < 4; t++)
#pragma unroll
                    for (int i = 0; i < 4; i++) sc[mb][t][i] = 0.f;

#pragma unroll
            for (int kk = 0; kk < 8; kk++) {
                const int ch = (kk << 1) + (tp & 1);
#pragma unroll
                for (int th = 0; th < 2; th++) {
                    int row = (h << 5) + (th << 4) + kb_row;
                    uint32_t addr = ksb +
                        (((row << 6) + ((ch ^ (row & 15)) << 2)) << 2);
                    uint32_t b0, b1, b2, b3;
                    ldsm_x4(b0, b1, b2, b3, addr);
                    mma_tf32(sc[0][2 * th + 0], aq[0][kk], b0, b1);
                    mma_tf32(sc[0][2 * th + 1], aq[0][kk], b2, b3);
                    mma_tf32(sc[1][2 * th + 0], aq[1][kk], b0, b1);
                    mma_tf32(sc[1][2 * th + 1], aq[1][kk], b2, b3);
                }
            }

#pragma unroll
            for (int mb = 0; mb < 2; mb++) {
                float rm0 = -1e30f, rm1 = -1e30f;
#pragma unroll
                for (int t = 0; t < 4; t++) {
                    rm0 = fmaxf(rm0, fmaxf(sc[mb][t][0], sc[mb][t][1]));
                    rm1 = fmaxf(rm1, fmaxf(sc[mb][t][2], sc[mb][t][3]));
                }
                rm0 = fmaxf(rm0, __shfl_xor_sync(0xffffffffu, rm0, 1));
                rm0 = fmaxf(rm0, __shfl_xor_sync(0xffffffffu, rm0, 2));
                rm1 = fmaxf(rm1, __shfl_xor_sync(0xffffffffu, rm1, 1));
                rm1 = fmaxf(rm1, __shfl_xor_sync(0xffffffffu, rm1, 2));

                float mn0 = fmaxf(m0[mb], rm0), mn1 = fmaxf(m1[mb], rm1);
                float al0 = __expf(m0[mb] - mn0), al1 = __expf(m1[mb] - mn1);
                float s0 = 0.f, s1 = 0.f;
#pragma unroll
                for (int t = 0; t < 4; t++) {
                    sc[mb][t][0] = __expf(sc[mb][t][0] - mn0);
                    sc[mb][t][1] = __expf(sc[mb][t][1] - mn0);
                    sc[mb][t][2] = __expf(sc[mb][t][2] - mn1);
                    sc[mb][t][3] = __expf(sc[mb][t][3] - mn1);
                    s0 += sc[mb][t][0] + sc[mb][t][1];
                    s1 += sc[mb][t][2] + sc[mb][t][3];
                }
                s0 += __shfl_xor_sync(0xffffffffu, s0, 1);
                s0 += __shfl_xor_sync(0xffffffffu, s0, 2);
                s1 += __shfl_xor_sync(0xffffffffu, s1, 1);
                s1 += __shfl_xor_sync(0xffffffffu, s1, 2);
                l0[mb] = l0[mb] * al0 + s0;  m0[mb] = mn0;
                l1[mb] = l1[mb] * al1 + s1;  m1[mb] = mn1;
#pragma unroll
                for (int t = 0; t < 8; t++) {
                    o[mb][t][0] *= al0; o[mb][t][1] *= al0;
                    o[mb][t][2] *= al1; o[mb][t][3] *= al1;
                }

#pragma unroll
                for (int t = 0; t < 4; t++) {
                    int col = (h << 5) + (t << 3) + (q << 1);
                    int ch = col >> 2, cl = col & 3;
                    int r0 = (mb << 4) + g;
                    int a0 = (r0 << 6) + ((ch ^ (r0 & 15)) << 2) + cl;
                    Pw[a0] = f2tf(sc[mb][t][0]);
                    Pw[a0 + 1] = f2tf(sc[mb][t][1]);
                    int r1 = r0 + 8;
                    int a1 = (r1 << 6) + ((ch ^ (r1 & 15)) << 2) + cl;
                    Pw[a1] = f2tf(sc[mb][t][2]);
                    Pw[a1 + 1] = f2tf(sc[mb][t][3]);
                }
            }
            __syncwarp();

#pragma unroll
            for (int kk = 0; kk < 4; kk++) {
                uint32_t ap[2][4];
                const int ch = (h << 3) + (kk << 1) + (tp >> 1);
#pragma unroll
                for (int mb = 0; mb < 2; mb++) {
                    int row = (mb << 4) + pa_row;
                    uint32_t addr = pwb +
                        (((row << 6) + ((ch ^ (row & 15)) << 2)) << 2);
                    ldsm_x4(ap[mb][0], ap[mb][1], ap[mb][2], ap[mb][3], addr);
                }
#pragma unroll
                for (int t = 0; t < 8; t++) {
                    int n = (t << 3) + g;
                    int vch = n >> 2, cl = n & 3;
                    int k0 = (h << 5) + (kk << 3) + q, k1 = k0 + 4;
                    uint32_t b0 = Vs[(k0 << 6) + ((vch ^ (k0 & 15)) << 2) + cl];
                    uint32_t b1 = Vs[(k1 << 6) + ((vch ^ (k1 & 15)) << 2) + cl];
                    mma_tf32(o[0][t], ap[0], b0, b1);
                    mma_tf32(o[1][t], ap[1], b0, b1);
                }
            }
        }
        __syncthreads();
    }

#pragma unroll
    for (int mb = 0; mb < 2; mb++) {
        float inv0 = 1.0f / l0[mb], inv1 = 1.0f / l1[mb];
        float* O0 = O + (size_t)(rowW + (mb << 4) + g) * DMODEL + head * HD;
        float* O1 = O0 + 8 * DMODEL;
#pragma unroll
        for (int t = 0; t < 8; t++) {
            int col = (t << 3) + (q << 1);
            *(float2*)(O0 + col) = make_float2(o[mb][t][0] * inv0, o[mb][t][1] * inv0);
            *(float2*)(O1 + col) = make_float2(o[mb][t][2] * inv1, o[mb][t][3] * inv1);
        }
    }
}

// ============================================================================
// kernel_launch
// ============================================================================
extern "C" void kernel_launch(void* const* d_in, const int* in_sizes, int n_in,
                              void* d_out, int out_size)
{
    const float* q  = (const float*)d_in[0];
    const float* k  = (const float*)d_in[1];
    const float* v  = (const float*)d_in[2];
    const float* Wq = (const float*)d_in[3];
    const float* Wk = (const float*)d_in[4];
    const float* Wv = (const float*)d_in[5];
    const float* Wo = (const float*)d_in[6];
    const float* bo = (const float*)d_in[7];

    const int S = in_sizes[0] / DMODEL;   // 4096

    float *pQ, *pK, *pV, *pAO, *pT1;
    cudaGetSymbolAddress((void**)&pQ,  g_Q);
    cudaGetSymbolAddress((void**)&pK,  g_K);
    cudaGetSymbolAddress((void**)&pV,  g_V);
    cudaGetSymbolAddress((void**)&pAO, g_AO);
    cudaGetSymbolAddress((void**)&pT1, g_T1);

    dim3 blk(256);

    // Fused Q/K/V projections: 768 CTAs (Q: *0.125+tf32; K/V: tf32)
    dim3 gq(24, S / 128);             // (24, 32)
    qkv_gemm_kernel<<<gq, blk>>>(q, k, v, Wq, Wk, Wv, pQ, pK, pV, S, DMODEL);

    // Attention (tf32, cp.async double buffer, 96KB dynamic smem)
    static bool attr_set = false;
    if (!attr_set) {
        cudaFuncSetAttribute(attn_tc_kernel,
                             cudaFuncAttributeMaxDynamicSharedMemorySize, 98304);
        attr_set = true;
    }
    dim3 ga(S / 128, NHEAD);          // (32, 8)
    attn_tc_kernel<<<ga, dim3(128), 98304>>>(pQ, pK, pV, pAO, S);

    // Output projection applied twice (plain fp32 out + bias), 256 CTAs each
    dim3 gp(DMODEL / 64, S / 128);    // (8, 32)
    gemm_tc_kernel<<<gp, blk>>>(pAO, Wo, pT1, bo, S, DMODEL, DMODEL);
    gemm_tc_kernel<<<gp, blk>>>(pT1, Wo, (float*)d_out, bo, S, DMODEL, DMODEL);
}